// round 6
// baseline (speedup 1.0000x reference)
#include <cuda_runtime.h>
#include <cuda_bf16.h>
#include <cstdint>
#include <math.h>

// Problem sizes (fixed by reference)
#define BB 16384
#define DD 512
#define RR 64
#define EE 8
#define NN 512   // = E*R = D

// ---------------- scratch (device globals; no allocs allowed) ----------------
__device__ float g_Vt[512 * 512];        // Vt[k*512+n] = V[n*512+k]   (k-major weights GEMM1)
__device__ float g_Ut[512 * 512];        // Ut[k*512+n] = UC[e][n][r], k=e*64+r (k-major GEMM2)
__device__ float g_gate[BB * 8];         // softmax gates
__device__ float g_gsum[BB];             // sum of gates per row
__device__ float g_gb[BB * 512];         // g @ b
__device__ float g_H[BB * 512];          // h = g * xv

// ---------------- small helpers ----------------
__device__ __forceinline__ unsigned long long pack2(float lo, float hi) {
    unsigned long long r;
    asm("mov.b64 %0, {%1, %2};" : "=l"(r) : "f"(lo), "f"(hi));
    return r;
}
__device__ __forceinline__ float2 u2f2(unsigned long long v) {
    float2 r;
    asm("mov.b64 {%0, %1}, %2;" : "=f"(r.x), "=f"(r.y) : "l"(v));
    return r;
}
// packed fp32x2 FMA: d = a*b + d   (sm_100+)
__device__ __forceinline__ void ffma2(unsigned long long& d, unsigned long long a, unsigned long long b) {
    asm("fma.rn.f32x2 %0, %1, %2, %0;" : "+l"(d) : "l"(a), "l"(b));
}
__device__ __forceinline__ void cp16(void* smem_dst, const void* gmem_src) {
    uint32_t s = (uint32_t)__cvta_generic_to_shared(smem_dst);
    asm volatile("cp.async.cg.shared.global [%0], [%1], 16;" :: "r"(s), "l"(gmem_src));
}

// ---------------- prep: transpose V to k-major ----------------
__global__ void vt_kernel(const float* __restrict__ V) {
    int idx = blockIdx.x * blockDim.x + threadIdx.x;   // 0 .. 512*512-1
    int k = idx >> 9, n = idx & 511;
    g_Vt[idx] = V[n * 512 + k];
}

// ---------------- prep: fold C into U -> Ut[k=(e,r)][n=d], k-major ----------------
__global__ void uc_kernel(const float* __restrict__ U, const float* __restrict__ C) {
    __shared__ float Cs[64][64];   // Cs[r][s]
    __shared__ float Us[64][65];   // Us[dl][s]
    int e = blockIdx.x;            // 0..7
    int d0 = blockIdx.y * 64;      // 0..511 step 64
    int t = threadIdx.x;           // 256 threads

    for (int i = t; i < 4096; i += 256) Cs[i >> 6][i & 63] = C[e * 4096 + i];
    for (int i = t; i < 4096; i += 256) Us[i >> 6][i & 63] = U[e * 32768 + d0 * 64 + i];
    __syncthreads();

    for (int o = t; o < 4096; o += 256) {
        int r = o >> 6, dl = o & 63;
        float s = 0.f;
#pragma unroll
        for (int ss = 0; ss < 64; ss++) s += Us[dl][ss] * Cs[r][ss];
        g_Ut[(e * 64 + r) * 512 + d0 + dl] = s;
    }
}

// ---------------- gate: softmax(x@Wg^T + bg), gsum, g@b ----------------
__global__ void gate_kernel(const float* __restrict__ x, const float* __restrict__ Wg,
                            const float* __restrict__ bg, const float* __restrict__ b) {
    int warp = blockIdx.x * (blockDim.x >> 5) + (threadIdx.x >> 5);
    int lane = threadIdx.x & 31;
    if (warp >= BB) return;
    int m = warp;

    const float4* xr = reinterpret_cast<const float4*>(x + (size_t)m * 512);
    float acc[8] = {0.f, 0.f, 0.f, 0.f, 0.f, 0.f, 0.f, 0.f};
#pragma unroll
    for (int i = 0; i < 4; i++) {
        float4 xv = xr[lane + i * 32];
#pragma unroll
        for (int e = 0; e < 8; e++) {
            float4 wv = reinterpret_cast<const float4*>(Wg + e * 512)[lane + i * 32];
            acc[e] += xv.x * wv.x + xv.y * wv.y + xv.z * wv.z + xv.w * wv.w;
        }
    }
#pragma unroll
    for (int off = 16; off; off >>= 1)
#pragma unroll
        for (int e = 0; e < 8; e++) acc[e] += __shfl_xor_sync(0xFFFFFFFFu, acc[e], off);

    // every lane now has all 8 logits; compute softmax redundantly
    float logit[8], mx = -1e30f;
#pragma unroll
    for (int e = 0; e < 8; e++) { logit[e] = acc[e] + bg[e]; mx = fmaxf(mx, logit[e]); }
    float ex[8], s = 0.f;
#pragma unroll
    for (int e = 0; e < 8; e++) { ex[e] = expf(logit[e] - mx); s += ex[e]; }
    float inv = 1.f / s;
    float gv[8], gs = 0.f;
#pragma unroll
    for (int e = 0; e < 8; e++) { gv[e] = ex[e] * inv; gs += gv[e]; }

    if (lane == 0) {
#pragma unroll
        for (int e = 0; e < 8; e++) g_gate[m * 8 + e] = gv[e];
        g_gsum[m] = gs;
    }

    // gb row = sum_e g_e * b[e,:]
#pragma unroll
    for (int i = 0; i < 4; i++) {
        float4 r = make_float4(0.f, 0.f, 0.f, 0.f);
#pragma unroll
        for (int e = 0; e < 8; e++) {
            float4 bv = reinterpret_cast<const float4*>(b + e * 512)[lane + i * 32];
            r.x += gv[e] * bv.x; r.y += gv[e] * bv.y; r.z += gv[e] * bv.z; r.w += gv[e] * bv.w;
        }
        reinterpret_cast<float4*>(g_gb + (size_t)m * 512)[lane + i * 32] = r;
    }
}

// ---------------- GEMM: C[M,N] = A[M,K] * Wt^T  (Wt stored k-major [K][N]) ----------------
// TM=128, TN=128, TK=16, 128 threads, 8x16 microtile (64 fp32x2 accumulators/thread).
// mode==1: GEMM1 (A=x param, Wt=g_Vt) epilogue h = g*xv -> g_H
// mode==2: GEMM2 (A=g_H,   Wt=g_Ut) epilogue out = x0*gproj + gb + x*gsum
__global__ __launch_bounds__(128) void gemm_kernel(const float* __restrict__ Ain, int mode,
                                                   const float* __restrict__ x0,
                                                   const float* __restrict__ x,
                                                   float* __restrict__ out) {
    __shared__ __align__(16) float As[2][128][16];   // m-major, XOR-swizzled k within row
    __shared__ __align__(16) float Ws[2][16][128];   // k-major rows

    const float* A  = (mode == 1) ? Ain  : g_H;
    const float* Wt = (mode == 1) ? g_Vt : g_Ut;

    const int tid = threadIdx.x;
    const int tx = tid & 7;        // 0..7  (column groups)
    const int ty = tid >> 3;       // 0..15 (row groups of 8)
    const int nb = blockIdx.x;     // 0..3
    const int mb = blockIdx.y;     // 0..127
    const int m0 = mb * 128, n0 = nb * 128;
    const int swz = (ty & 3) << 2;

    unsigned long long acc[8][8];
#pragma unroll
    for (int i = 0; i < 8; i++)
#pragma unroll
        for (int p = 0; p < 8; p++) acc[i][p] = 0ull;

#define LOAD_STAGE(BUF, KB)                                                              \
    {                                                                                    \
        _Pragma("unroll")                                                                \
        for (int j = 0; j < 4; j++) {                                                    \
            int f = tid + j * 128;                                                       \
            int am = f >> 2, akq = (f & 3) << 2;                                         \
            cp16(&As[BUF][am][akq ^ (((am >> 3) & 3) << 2)],                             \
                 A + (size_t)(m0 + am) * 512 + (KB) * 16 + akq);                         \
            int wk = f >> 5, wn = (f & 31) << 2;                                         \
            cp16(&Ws[BUF][wk][wn], Wt + (size_t)((KB) * 16 + wk) * 512 + n0 + wn);       \
        }                                                                                \
        asm volatile("cp.async.commit_group;");                                          \
    }

    LOAD_STAGE(0, 0)

    const int NBK = 32;  // 512 / 16
    for (int kb = 0; kb < NBK; kb++) {
        int buf = kb & 1;
        if (kb + 1 < NBK) {
            LOAD_STAGE(buf ^ 1, kb + 1)
            asm volatile("cp.async.wait_group 1;");
        } else {
            asm volatile("cp.async.wait_group 0;");
        }
        __syncthreads();

#pragma unroll
        for (int k = 0; k < 16; k++) {
            const int kk = k ^ swz;
            unsigned long long a2[8];
#pragma unroll
            for (int i = 0; i < 8; i++) {
                float av = As[buf][ty * 8 + i][kk];
                a2[i] = pack2(av, av);
            }
            unsigned long long w2[8];
#pragma unroll
            for (int g = 0; g < 4; g++) {
                ulonglong2 wv = *reinterpret_cast<const ulonglong2*>(&Ws[buf][k][g * 32 + tx * 4]);
                w2[2 * g] = wv.x; w2[2 * g + 1] = wv.y;
            }
#pragma unroll
            for (int i = 0; i < 8; i++)
#pragma unroll
                for (int p = 0; p < 8; p++) ffma2(acc[i][p], a2[i], w2[p]);
        }
        __syncthreads();
    }
#undef LOAD_STAGE

    if (mode == 1) {
        // h = g[m, e] * xv ; e = nb*2 + (g>>1) for this thread's column groups
#pragma unroll
        for (int i = 0; i < 8; i++) {
            int m = m0 + ty * 8 + i;
            float2 gp = *reinterpret_cast<const float2*>(g_gate + m * 8 + nb * 2);
#pragma unroll
            for (int g = 0; g < 4; g++) {
                float gv = (g < 2) ? gp.x : gp.y;
                float2 v0 = u2f2(acc[i][2 * g]);
                float2 v1 = u2f2(acc[i][2 * g + 1]);
                float4 hv = make_float4(v0.x * gv, v0.y * gv, v1.x * gv, v1.y * gv);
                *reinterpret_cast<float4*>(g_H + (size_t)m * 512 + n0 + g * 32 + tx * 4) = hv;
            }
        }
    } else {
        // out = x0*gproj + gb + x*gsum
#pragma unroll
        for (int i = 0; i < 8; i++) {
            int m = m0 + ty * 8 + i;
            float gs = g_gsum[m];
#pragma unroll
            for (int g = 0; g < 4; g++) {
                size_t off = (size_t)m * 512 + n0 + g * 32 + tx * 4;
                float4 xv0 = *reinterpret_cast<const float4*>(x0 + off);
                float4 xv  = *reinterpret_cast<const float4*>(x + off);
                float4 gbv = *reinterpret_cast<const float4*>(g_gb + off);
                float2 v0 = u2f2(acc[i][2 * g]);
                float2 v1 = u2f2(acc[i][2 * g + 1]);
                float4 o;
                o.x = fmaf(xv0.x, v0.x, fmaf(xv.x, gs, gbv.x));
                o.y = fmaf(xv0.y, v0.y, fmaf(xv.y, gs, gbv.y));
                o.z = fmaf(xv0.z, v1.x, fmaf(xv.z, gs, gbv.z));
                o.w = fmaf(xv0.w, v1.y, fmaf(xv.w, gs, gbv.w));
                *reinterpret_cast<float4*>(out + off) = o;
            }
        }
    }
}

// ---------------- launch ----------------
extern "C" void kernel_launch(void* const* d_in, const int* in_sizes, int n_in,
                              void* d_out, int out_size) {
    const float* x0 = (const float*)d_in[0];   // [B, D]
    const float* x  = (const float*)d_in[1];   // [B, D]
    const float* U  = (const float*)d_in[2];   // [E, D, R]
    const float* V  = (const float*)d_in[3];   // [E, R, D]
    const float* C  = (const float*)d_in[4];   // [E, R, R]
    const float* b  = (const float*)d_in[5];   // [E, D]
    const float* Wg = (const float*)d_in[6];   // [E, D]
    const float* bg = (const float*)d_in[7];   // [E]
    float* out = (float*)d_out;

    // weight prep (cheap, L2-resident)
    vt_kernel<<<512, 512>>>(V);
    uc_kernel<<<dim3(8, 8), 256>>>(U, C);

    // gate + g@b
    gate_kernel<<<2048, 256>>>(x, Wg, bg, b);

    // GEMM1: h = g * (x @ Vflat^T)
    gemm_kernel<<<dim3(4, 128), 128>>>(x, 1, nullptr, nullptr, nullptr);

    // GEMM2: out = x0 * (h @ UCflat^T) + g@b + x*gsum
    gemm_kernel<<<dim3(4, 128), 128>>>(nullptr, 2, x0, x, out);
}

// round 8
// speedup vs baseline: 1.6487x; 1.6487x over previous
#include <cuda_runtime.h>
#include <cuda_bf16.h>
#include <cstdint>
#include <math.h>

// Problem sizes (fixed)
#define BB 16384
#define DD 512

// ---------------- scratch (device globals; no allocs allowed) ----------------
__device__ float g_Ut[512 * 512];   // B operand GEMM2: Ut[n=d][k=e*64+r] = sum_s U[e,d,s]*C[e,r,s]
__device__ float g_gate[BB * 8];    // softmax gates
__device__ float g_H[BB * 512];     // h = g * xv (GEMM1 output, GEMM2 A operand)

// ---------------- helpers ----------------
__device__ __forceinline__ uint32_t smem_u32(const void* p) {
    uint32_t a;
    asm("{ .reg .u64 t; cvta.to.shared.u64 t, %1; cvt.u32.u64 %0, t; }" : "=r"(a) : "l"(p));
    return a;
}
__device__ __forceinline__ void cp16s(uint32_t s, const void* g) {
    asm volatile("cp.async.cg.shared.global [%0], [%1], 16;" :: "r"(s), "l"(g));
}
// m16n8k8 tf32 MMA, acc += A*B (fp32 bits fed as tf32; HW truncates mantissa)
__device__ __forceinline__ void mma_tf32(float* d, const uint32_t* a, uint32_t b0, uint32_t b1) {
    asm volatile(
        "mma.sync.aligned.m16n8k8.row.col.f32.tf32.tf32.f32 "
        "{%0,%1,%2,%3}, {%4,%5,%6,%7}, {%8,%9}, {%0,%1,%2,%3};"
        : "+f"(d[0]), "+f"(d[1]), "+f"(d[2]), "+f"(d[3])
        : "r"(a[0]), "r"(a[1]), "r"(a[2]), "r"(a[3]), "r"(b0), "r"(b1));
}

// smem: As[2][128][36] | Bs[2][128][36]  floats
static constexpr int ROWF = 36;                   // padded row stride (floats)
static constexpr int BUF_F = 128 * ROWF;          // floats per buffer
static constexpr int SM_TOTAL = 4 * BUF_F * 4;    // bytes = 73728

// ---------------- prep: fold C into U -> Ut[n=d][k=e*64+r] ----------------
__global__ void uc_kernel(const float* __restrict__ U, const float* __restrict__ C) {
    __shared__ float Cs[64][64];   // Cs[r][s]
    __shared__ float Us[64][65];   // Us[dl][s]
    int e = blockIdx.x;            // 0..7
    int d0 = blockIdx.y * 64;      // 0..511 step 64
    int t = threadIdx.x;           // 256 threads

    for (int i = t; i < 4096; i += 256) Cs[i >> 6][i & 63] = C[e * 4096 + i];
    for (int i = t; i < 4096; i += 256) Us[i >> 6][i & 63] = U[e * 32768 + d0 * 64 + i];
    __syncthreads();

    for (int o = t; o < 4096; o += 256) {
        int r = o >> 6, dl = o & 63;
        float s = 0.f;
#pragma unroll
        for (int ss = 0; ss < 64; ss++) s += Us[dl][ss] * Cs[r][ss];
        g_Ut[(size_t)(d0 + dl) * 512 + e * 64 + r] = s;
    }
}

// ---------------- gate: g = softmax(x@Wg^T + bg) ----------------
__global__ void gate_kernel(const float* __restrict__ x, const float* __restrict__ Wg,
                            const float* __restrict__ bg) {
    int warp = blockIdx.x * (blockDim.x >> 5) + (threadIdx.x >> 5);
    int lane = threadIdx.x & 31;
    if (warp >= BB) return;
    int m = warp;

    const float4* xr = reinterpret_cast<const float4*>(x + (size_t)m * 512);
    float acc[8] = {0.f, 0.f, 0.f, 0.f, 0.f, 0.f, 0.f, 0.f};
#pragma unroll
    for (int i = 0; i < 4; i++) {
        float4 xv = xr[lane + i * 32];
#pragma unroll
        for (int e = 0; e < 8; e++) {
            float4 wv = reinterpret_cast<const float4*>(Wg + e * 512)[lane + i * 32];
            acc[e] += xv.x * wv.x + xv.y * wv.y + xv.z * wv.z + xv.w * wv.w;
        }
    }
#pragma unroll
    for (int off = 16; off; off >>= 1)
#pragma unroll
        for (int e = 0; e < 8; e++) acc[e] += __shfl_xor_sync(0xFFFFFFFFu, acc[e], off);

    if (lane == 0) {
        float logit[8], mx = -1e30f;
#pragma unroll
        for (int e = 0; e < 8; e++) { logit[e] = acc[e] + bg[e]; mx = fmaxf(mx, logit[e]); }
        float ex[8], s = 0.f;
#pragma unroll
        for (int e = 0; e < 8; e++) { ex[e] = expf(logit[e] - mx); s += ex[e]; }
        float inv = 1.f / s;
#pragma unroll
        for (int e = 0; e < 8; e++) g_gate[m * 8 + e] = ex[e] * inv;
    }
}

// ---------------- tf32 mma.sync GEMM ----------------
// D[128,128] tile of A[M,512] @ B[n,k]^T; 256 thr, warp grid 2(m)x4(n), warp tile 64x32.
// K-permutation within each k8 step: logical col c -> phys (c<4 ? 2c : 2(c-4)+1), so
// each thread's fragment pair (c, c+4) is an adjacent float2 in smem (LDS.64).
// mode 1: A=x, B=V [n=(e,r)][k=d]; epilogue h = g*xv -> g_H
// mode 2: A=g_H, B=g_Ut [n=d][k=(e,r)]; epilogue out = x0*gproj + g@b + x*sum(g)
__global__ __launch_bounds__(256) void gemm_mma(const float* __restrict__ Ain,
                                                const float* __restrict__ Bin,
                                                int mode,
                                                const float* __restrict__ x0,
                                                const float* __restrict__ x,
                                                const float* __restrict__ bbias,
                                                float* __restrict__ out) {
    extern __shared__ __align__(16) float smemf[];
    const uint32_t sb = smem_u32(smemf);
    const int tid = threadIdx.x;
    const int wid = tid >> 5, lane = tid & 31;
    const int g = lane >> 2, tg = lane & 3;       // groupID, thread-in-group
    const int wm = wid & 1, wn = wid >> 1;        // warp m (0..1), n (0..3)
    const int n0 = blockIdx.x * 128, m0 = blockIdx.y * 128;

    const float* A  = (mode == 1) ? Ain : g_H;
    const float* Bp = (mode == 1) ? Bin : g_Ut;

    float acc[4][4][4];
#pragma unroll
    for (int mi = 0; mi < 4; mi++)
#pragma unroll
        for (int ni = 0; ni < 4; ni++)
#pragma unroll
            for (int q = 0; q < 4; q++) acc[mi][ni][q] = 0.f;

    // chunk = 128 rows x 32 floats (k). 1024 x 16B segments per operand, 4 per thread.
#define LOADCHUNK(BUF, KC) do {                                                          \
        const float* _ag = A  + (size_t)m0 * 512 + (KC) * 32;                            \
        const float* _bg = Bp + (size_t)n0 * 512 + (KC) * 32;                            \
        uint32_t _ab = sb + (BUF) * (BUF_F * 4);                                         \
        uint32_t _bb = sb + (2 * BUF_F + (BUF) * BUF_F) * 4;                             \
        _Pragma("unroll")                                                                \
        for (int j = 0; j < 4; j++) {                                                    \
            int id = tid + j * 256;                                                      \
            int row = id >> 3, seg = id & 7;                                             \
            cp16s(_ab + row * (ROWF * 4) + seg * 16, _ag + (size_t)row * 512 + seg * 4); \
            cp16s(_bb + row * (ROWF * 4) + seg * 16, _bg + (size_t)row * 512 + seg * 4); \
        }                                                                                \
        asm volatile("cp.async.commit_group;");                                          \
    } while (0)

    LOADCHUNK(0, 0);

    for (int c = 0; c < 16; c++) {
        const int buf = c & 1;
        if (c < 15) LOADCHUNK(buf ^ 1, c + 1);
        if (c < 15) asm volatile("cp.async.wait_group 1;");
        else        asm volatile("cp.async.wait_group 0;");
        __syncthreads();

        const float* Asb = smemf + buf * BUF_F;
        const float* Bsb = smemf + 2 * BUF_F + buf * BUF_F;

#pragma unroll
        for (int ks = 0; ks < 4; ks++) {
            const int kcol = ks * 8 + 2 * tg;
            uint32_t a[4][4];
#pragma unroll
            for (int mi = 0; mi < 4; mi++) {
                const int rbase = wm * 64 + mi * 16 + g;
                float2 lo = *reinterpret_cast<const float2*>(&Asb[rbase * ROWF + kcol]);
                float2 hi = *reinterpret_cast<const float2*>(&Asb[(rbase + 8) * ROWF + kcol]);
                a[mi][0] = __float_as_uint(lo.x);
                a[mi][1] = __float_as_uint(hi.x);
                a[mi][2] = __float_as_uint(lo.y);
                a[mi][3] = __float_as_uint(hi.y);
            }
#pragma unroll
            for (int ni = 0; ni < 4; ni++) {
                const int nrow = wn * 32 + ni * 8 + g;
                float2 bv = *reinterpret_cast<const float2*>(&Bsb[nrow * ROWF + kcol]);
                uint32_t b0 = __float_as_uint(bv.x), b1 = __float_as_uint(bv.y);
#pragma unroll
                for (int mi = 0; mi < 4; mi++) mma_tf32(acc[mi][ni], a[mi], b0, b1);
            }
        }
        __syncthreads();
    }
#undef LOADCHUNK

    // ---------------- epilogue ----------------
    // acc[mi][ni]: rows r0 = m0+wm*64+mi*16+g (c0,c1), r1 = r0+8 (c2,c3);
    // cols = n0 + wn*32 + ni*8 + 2*tg (+1)
    if (mode == 1) {
        const int e_w = (n0 + wn * 32) >> 6;   // expert constant per warp-column
#pragma unroll
        for (int mi = 0; mi < 4; mi++) {
            int r0 = m0 + wm * 64 + mi * 16 + g, r1 = r0 + 8;
            float g0 = g_gate[r0 * 8 + e_w];
            float g1 = g_gate[r1 * 8 + e_w];
#pragma unroll
            for (int ni = 0; ni < 4; ni++) {
                int cc = n0 + wn * 32 + ni * 8 + 2 * tg;
                float2 v0 = make_float2(g0 * acc[mi][ni][0], g0 * acc[mi][ni][1]);
                float2 v1 = make_float2(g1 * acc[mi][ni][2], g1 * acc[mi][ni][3]);
                *reinterpret_cast<float2*>(&g_H[(size_t)r0 * 512 + cc]) = v0;
                *reinterpret_cast<float2*>(&g_H[(size_t)r1 * 512 + cc]) = v1;
            }
        }
    } else {
        // stage b columns for this CTA: bs[e][0..127]
        __syncthreads();
        float* bs = smemf;
        for (int i = tid; i < 8 * 128; i += 256)
            bs[i] = bbias[(i >> 7) * 512 + n0 + (i & 127)];
        __syncthreads();

#pragma unroll
        for (int ni = 0; ni < 4; ni++) {
            int cl = wn * 32 + ni * 8 + 2 * tg;
            int cc = n0 + cl;
            float bc0[8], bc1[8];
#pragma unroll
            for (int e = 0; e < 8; e++) { bc0[e] = bs[e * 128 + cl]; bc1[e] = bs[e * 128 + cl + 1]; }
#pragma unroll
            for (int mi = 0; mi < 4; mi++) {
                int r0 = m0 + wm * 64 + mi * 16 + g, r1 = r0 + 8;
#pragma unroll
                for (int rr = 0; rr < 2; rr++) {
                    int r = rr ? r1 : r0;
                    float4 ga = *reinterpret_cast<const float4*>(g_gate + r * 8);
                    float4 gb = *reinterpret_cast<const float4*>(g_gate + r * 8 + 4);
                    float gs = ga.x + ga.y + ga.z + ga.w + gb.x + gb.y + gb.z + gb.w;
                    float q0 = ga.x * bc0[0] + ga.y * bc0[1] + ga.z * bc0[2] + ga.w * bc0[3]
                             + gb.x * bc0[4] + gb.y * bc0[5] + gb.z * bc0[6] + gb.w * bc0[7];
                    float q1 = ga.x * bc1[0] + ga.y * bc1[1] + ga.z * bc1[2] + ga.w * bc1[3]
                             + gb.x * bc1[4] + gb.y * bc1[5] + gb.z * bc1[6] + gb.w * bc1[7];
                    size_t off = (size_t)r * 512 + cc;
                    float2 xv0 = *reinterpret_cast<const float2*>(x0 + off);
                    float2 xv  = *reinterpret_cast<const float2*>(x + off);
                    float a0 = acc[mi][ni][rr ? 2 : 0];
                    float a1 = acc[mi][ni][rr ? 3 : 1];
                    float2 o;
                    o.x = fmaf(xv0.x, a0, fmaf(xv.x, gs, q0));
                    o.y = fmaf(xv0.y, a1, fmaf(xv.y, gs, q1));
                    *reinterpret_cast<float2*>(out + off) = o;
                }
            }
        }
    }
}

// ---------------- launch ----------------
extern "C" void kernel_launch(void* const* d_in, const int* in_sizes, int n_in,
                              void* d_out, int out_size) {
    const float* x0 = (const float*)d_in[0];   // [B, D]
    const float* x  = (const float*)d_in[1];   // [B, D]
    const float* U  = (const float*)d_in[2];   // [E, D, R]
    const float* V  = (const float*)d_in[3];   // [E, R, D]  (native B operand for GEMM1)
    const float* C  = (const float*)d_in[4];   // [E, R, R]
    const float* b  = (const float*)d_in[5];   // [E, D]
    const float* Wg = (const float*)d_in[6];   // [E, D]
    const float* bg = (const float*)d_in[7];   // [E]
    float* out = (float*)d_out;

    cudaFuncSetAttribute(gemm_mma, cudaFuncAttributeMaxDynamicSharedMemorySize, SM_TOTAL);

    uc_kernel<<<dim3(8, 8), 256>>>(U, C);
    gate_kernel<<<2048, 256>>>(x, Wg, bg);

    // GEMM1: g_H = g * (x @ Vflat^T)
    gemm_mma<<<dim3(4, 128), 256, SM_TOTAL>>>(x, V, 1, nullptr, nullptr, nullptr, nullptr);
    // GEMM2: out = x0 * (g_H @ Ut^T) + g@b + x*sum(g)
    gemm_mma<<<dim3(4, 128), 256, SM_TOTAL>>>(nullptr, nullptr, 2, x0, x, b, out);
}

// round 9
// speedup vs baseline: 2.6130x; 1.5849x over previous
#include <cuda_runtime.h>
#include <cuda_bf16.h>
#include <cstdint>
#include <math.h>

// Problem sizes (fixed)
#define BB 16384
#define DD 512

// ---------------- scratch (device globals; no allocs allowed) ----------------
__device__ __nv_bfloat16 g_Vb[512 * 512];    // B1: V bf16, rows n=(e,r), k=d contiguous
__device__ __nv_bfloat16 g_Utb[512 * 512];   // B2: Ut[n=d][k=e*64+r] bf16 (C folded into U)
__device__ __nv_bfloat16 g_Xb[BB * 512];     // x bf16 (A operand GEMM1)
__device__ __nv_bfloat16 g_Hb[BB * 512];     // h = g*xv bf16 (A operand GEMM2)
__device__ float g_gate[BB * 8];             // softmax gates

// ---------------- helpers ----------------
__device__ __forceinline__ uint32_t smem_u32(const void* p) {
    uint32_t a;
    asm("{ .reg .u64 t; cvta.to.shared.u64 t, %1; cvt.u32.u64 %0, t; }" : "=r"(a) : "l"(p));
    return a;
}
__device__ __forceinline__ void cp16s(uint32_t s, const void* g) {
    asm volatile("cp.async.cg.shared.global [%0], [%1], 16;" :: "r"(s), "l"(g));
}
__device__ __forceinline__ void ldsm4(uint32_t* r, uint32_t addr) {
    asm volatile("ldmatrix.sync.aligned.m8n8.x4.shared.b16 {%0,%1,%2,%3}, [%4];"
        : "=r"(r[0]), "=r"(r[1]), "=r"(r[2]), "=r"(r[3]) : "r"(addr));
}
// m16n8k16 bf16 MMA, fp32 accum
__device__ __forceinline__ void mma_bf16(float* d, const uint32_t* a, uint32_t b0, uint32_t b1) {
    asm volatile(
        "mma.sync.aligned.m16n8k16.row.col.f32.bf16.bf16.f32 "
        "{%0,%1,%2,%3}, {%4,%5,%6,%7}, {%8,%9}, {%0,%1,%2,%3};"
        : "+f"(d[0]), "+f"(d[1]), "+f"(d[2]), "+f"(d[3])
        : "r"(a[0]), "r"(a[1]), "r"(a[2]), "r"(a[3]), "r"(b0), "r"(b1));
}

// smem geometry: chunk = 128 rows x 64 bf16 (128B) per operand, padded to 144B/row.
static constexpr int ROWB = 144;                 // bytes per smem row (9 x 16B -> conflict-free)
static constexpr int STAGE_B = 128 * ROWB;       // 18432 B per operand per stage
static constexpr int OPS_B = 2 * STAGE_B;        // 36864 B per stage (A + B)
static constexpr int NSTAGE = 3;
static constexpr int SM_TOTAL = NSTAGE * OPS_B;  // 110592 B

// ---------------- convert fp32 -> bf16 (vectorized) ----------------
__global__ void cvt_kernel(const float4* __restrict__ in, uint2* __restrict__ out, int n4) {
    int i = blockIdx.x * blockDim.x + threadIdx.x;
    if (i >= n4) return;
    float4 v = in[i];
    __nv_bfloat162 lo = __floats2bfloat162_rn(v.x, v.y);
    __nv_bfloat162 hi = __floats2bfloat162_rn(v.z, v.w);
    uint2 o;
    o.x = *reinterpret_cast<uint32_t*>(&lo);
    o.y = *reinterpret_cast<uint32_t*>(&hi);
    out[i] = o;
}

// ---------------- prep: fold C into U -> Utb[n=d][k=e*64+r] (bf16) ----------------
__global__ void uc_kernel(const float* __restrict__ U, const float* __restrict__ C) {
    __shared__ float Cs[64][64];   // Cs[r][s]
    __shared__ float Us[64][65];   // Us[dl][s]
    int e = blockIdx.x;            // 0..7
    int d0 = blockIdx.y * 64;      // 0..511 step 64
    int t = threadIdx.x;           // 256 threads

    for (int i = t; i < 4096; i += 256) Cs[i >> 6][i & 63] = C[e * 4096 + i];
    for (int i = t; i < 4096; i += 256) Us[i >> 6][i & 63] = U[e * 32768 + d0 * 64 + i];
    __syncthreads();

    for (int o = t; o < 4096; o += 256) {
        int r = o >> 6, dl = o & 63;
        float s = 0.f;
#pragma unroll
        for (int ss = 0; ss < 64; ss++) s += Us[dl][ss] * Cs[r][ss];
        g_Utb[(size_t)(d0 + dl) * 512 + e * 64 + r] = __float2bfloat16(s);
    }
}

// ---------------- gate: g = softmax(x@Wg^T + bg) ----------------
__global__ void gate_kernel(const float* __restrict__ x, const float* __restrict__ Wg,
                            const float* __restrict__ bg) {
    int warp = blockIdx.x * (blockDim.x >> 5) + (threadIdx.x >> 5);
    int lane = threadIdx.x & 31;
    if (warp >= BB) return;
    int m = warp;

    const float4* xr = reinterpret_cast<const float4*>(x + (size_t)m * 512);
    float acc[8] = {0.f, 0.f, 0.f, 0.f, 0.f, 0.f, 0.f, 0.f};
#pragma unroll
    for (int i = 0; i < 4; i++) {
        float4 xv = xr[lane + i * 32];
#pragma unroll
        for (int e = 0; e < 8; e++) {
            float4 wv = reinterpret_cast<const float4*>(Wg + e * 512)[lane + i * 32];
            acc[e] += xv.x * wv.x + xv.y * wv.y + xv.z * wv.z + xv.w * wv.w;
        }
    }
#pragma unroll
    for (int off = 16; off; off >>= 1)
#pragma unroll
        for (int e = 0; e < 8; e++) acc[e] += __shfl_xor_sync(0xFFFFFFFFu, acc[e], off);

    if (lane == 0) {
        float logit[8], mx = -1e30f;
#pragma unroll
        for (int e = 0; e < 8; e++) { logit[e] = acc[e] + bg[e]; mx = fmaxf(mx, logit[e]); }
        float ex[8], s = 0.f;
#pragma unroll
        for (int e = 0; e < 8; e++) { ex[e] = expf(logit[e] - mx); s += ex[e]; }
        float inv = 1.f / s;
#pragma unroll
        for (int e = 0; e < 8; e++) g_gate[m * 8 + e] = ex[e] * inv;
    }
}

// ---------------- bf16 mma.sync GEMM ----------------
// D[128,128] tile of A[M,512] @ B[n,k]^T (both bf16, k-contiguous rows).
// 256 thr, warp grid 2(m) x 4(n), warp tile 64x32. K chunks of 64, 3-stage cp.async,
// one __syncthreads per chunk. ldmatrix.x4 fragment loads.
// mode 1: A=g_Xb, B=g_Vb; epilogue h = g*xv -> g_Hb (bf16)
// mode 2: A=g_Hb, B=g_Utb; epilogue out = x0*gproj + g@b + x*sum(g)
__global__ __launch_bounds__(256) void gemm_mma(const __nv_bfloat16* __restrict__ A,
                                                const __nv_bfloat16* __restrict__ Bp,
                                                int mode,
                                                const float* __restrict__ x0,
                                                const float* __restrict__ x,
                                                const float* __restrict__ bbias,
                                                float* __restrict__ out) {
    extern __shared__ __align__(16) float smemf[];
    const uint32_t sb = smem_u32(smemf);
    const int tid = threadIdx.x;
    const int wid = tid >> 5, lane = tid & 31;
    const int g = lane >> 2, tg = lane & 3;       // accum frag coords
    const int wm = wid & 1, wn = wid >> 1;        // warp m (0..1), n (0..3)
    const int n0 = blockIdx.x * 128, m0 = blockIdx.y * 128;

    float acc[4][4][4];
#pragma unroll
    for (int mi = 0; mi < 4; mi++)
#pragma unroll
        for (int ni = 0; ni < 4; ni++)
#pragma unroll
            for (int q = 0; q < 4; q++) acc[mi][ni][q] = 0.f;

    // ldmatrix lane->address maps (within a stage; add stage*OPS_B + ks*32 at use)
    // A x4 (m16 x k16): matrices [m0-7,k0-7],[m8-15,k0-7],[m0-7,k8-15],[m8-15,k8-15]
    const int arow_l = (lane & 7) + ((lane >> 3) & 1) * 8;
    const int ahalf  = ((lane >> 4) & 1) * 16;
    uint32_t a_addr[4];
#pragma unroll
    for (int mi = 0; mi < 4; mi++)
        a_addr[mi] = sb + (uint32_t)(wm * 64 + mi * 16 + arow_l) * ROWB + ahalf;
    // B x4 (n16 x k16): matrices [n0-7,k0-7],[n0-7,k8-15],[n8-15,k0-7],[n8-15,k8-15]
    const int brow_l = (lane & 7) + ((lane >> 4) & 1) * 8;
    const int bhalf  = ((lane >> 3) & 1) * 16;
    uint32_t b_addr[2];
#pragma unroll
    for (int bj = 0; bj < 2; bj++)
        b_addr[bj] = sb + STAGE_B + (uint32_t)(wn * 32 + bj * 16 + brow_l) * ROWB + bhalf;

    // chunk load: 128 rows x 128B per operand; 8 segs/row; 8 cp.async per thread
#define LOADCHUNK(SLOT, KC) do {                                                         \
        const __nv_bfloat16* _ag = A  + (size_t)m0 * 512 + (KC) * 64;                    \
        const __nv_bfloat16* _bg = Bp + (size_t)n0 * 512 + (KC) * 64;                    \
        uint32_t _ab = sb + (SLOT) * OPS_B;                                              \
        uint32_t _bb = _ab + STAGE_B;                                                    \
        _Pragma("unroll")                                                                \
        for (int j = 0; j < 4; j++) {                                                    \
            int id = tid + j * 256;                                                      \
            int row = id >> 3, seg = id & 7;                                             \
            cp16s(_ab + row * ROWB + seg * 16, _ag + (size_t)row * 512 + seg * 8);       \
            cp16s(_bb + row * ROWB + seg * 16, _bg + (size_t)row * 512 + seg * 8);       \
        }                                                                                \
        asm volatile("cp.async.commit_group;");                                          \
    } while (0)

    LOADCHUNK(0, 0);
    LOADCHUNK(1, 1);

    for (int c = 0; c < 8; c++) {
        if (c < 7) asm volatile("cp.async.wait_group 1;");
        else       asm volatile("cp.async.wait_group 0;");
        __syncthreads();
        if (c + 2 < 8) LOADCHUNK((c + 2) % 3, c + 2);

        const uint32_t soff = (uint32_t)(c % 3) * OPS_B;
#pragma unroll
        for (int ks = 0; ks < 4; ks++) {
            const uint32_t ko = soff + ks * 32;
            uint32_t a[4][4];
#pragma unroll
            for (int mi = 0; mi < 4; mi++) ldsm4(a[mi], a_addr[mi] + ko);
            uint32_t b[2][4];
#pragma unroll
            for (int bj = 0; bj < 2; bj++) ldsm4(b[bj], b_addr[bj] + ko);
#pragma unroll
            for (int ni = 0; ni < 4; ni++) {
                uint32_t b0 = b[ni >> 1][(ni & 1) * 2];
                uint32_t b1 = b[ni >> 1][(ni & 1) * 2 + 1];
#pragma unroll
                for (int mi = 0; mi < 4; mi++) mma_bf16(acc[mi][ni], a[mi], b0, b1);
            }
        }
    }
#undef LOADCHUNK

    // ---------------- epilogue ----------------
    // acc[mi][ni]: rows r0 = m0+wm*64+mi*16+g (c0,c1), r1 = r0+8 (c2,c3);
    // cols = n0 + wn*32 + ni*8 + 2*tg (+1)
    if (mode == 1) {
        const int e_w = (n0 + wn * 32) >> 6;   // expert constant per warp column strip
#pragma unroll
        for (int mi = 0; mi < 4; mi++) {
            int r0 = m0 + wm * 64 + mi * 16 + g, r1 = r0 + 8;
            float g0 = g_gate[r0 * 8 + e_w];
            float g1 = g_gate[r1 * 8 + e_w];
#pragma unroll
            for (int ni = 0; ni < 4; ni++) {
                int cc = n0 + wn * 32 + ni * 8 + 2 * tg;
                __nv_bfloat162 h0 = __floats2bfloat162_rn(g0 * acc[mi][ni][0], g0 * acc[mi][ni][1]);
                __nv_bfloat162 h1 = __floats2bfloat162_rn(g1 * acc[mi][ni][2], g1 * acc[mi][ni][3]);
                *reinterpret_cast<__nv_bfloat162*>(&g_Hb[(size_t)r0 * 512 + cc]) = h0;
                *reinterpret_cast<__nv_bfloat162*>(&g_Hb[(size_t)r1 * 512 + cc]) = h1;
            }
        }
    } else {
        // stage b columns for this CTA: bs[e][0..127]
        __syncthreads();
        float* bs = smemf;
        for (int i = tid; i < 8 * 128; i += 256)
            bs[i] = bbias[(i >> 7) * 512 + n0 + (i & 127)];
        __syncthreads();

#pragma unroll
        for (int ni = 0; ni < 4; ni++) {
            int cl = wn * 32 + ni * 8 + 2 * tg;
            int cc = n0 + cl;
            float bc0[8], bc1[8];
#pragma unroll
            for (int e = 0; e < 8; e++) { bc0[e] = bs[e * 128 + cl]; bc1[e] = bs[e * 128 + cl + 1]; }
#pragma unroll
            for (int mi = 0; mi < 4; mi++) {
                int r0 = m0 + wm * 64 + mi * 16 + g;
#pragma unroll
                for (int rr = 0; rr < 2; rr++) {
                    int r = r0 + rr * 8;
                    float4 ga = *reinterpret_cast<const float4*>(g_gate + r * 8);
                    float4 gb = *reinterpret_cast<const float4*>(g_gate + r * 8 + 4);
                    float gs = ga.x + ga.y + ga.z + ga.w + gb.x + gb.y + gb.z + gb.w;
                    float q0 = ga.x * bc0[0] + ga.y * bc0[1] + ga.z * bc0[2] + ga.w * bc0[3]
                             + gb.x * bc0[4] + gb.y * bc0[5] + gb.z * bc0[6] + gb.w * bc0[7];
                    float q1 = ga.x * bc1[0] + ga.y * bc1[1] + ga.z * bc1[2] + ga.w * bc1[3]
                             + gb.x * bc1[4] + gb.y * bc1[5] + gb.z * bc1[6] + gb.w * bc1[7];
                    size_t off = (size_t)r * 512 + cc;
                    float2 xv0 = *reinterpret_cast<const float2*>(x0 + off);
                    float2 xv  = *reinterpret_cast<const float2*>(x + off);
                    float a0 = acc[mi][ni][rr ? 2 : 0];
                    float a1 = acc[mi][ni][rr ? 3 : 1];
                    float2 o;
                    o.x = fmaf(xv0.x, a0, fmaf(xv.x, gs, q0));
                    o.y = fmaf(xv0.y, a1, fmaf(xv.y, gs, q1));
                    *reinterpret_cast<float2*>(out + off) = o;
                }
            }
        }
    }
}

// ---------------- launch ----------------
extern "C" void kernel_launch(void* const* d_in, const int* in_sizes, int n_in,
                              void* d_out, int out_size) {
    const float* x0 = (const float*)d_in[0];   // [B, D]
    const float* x  = (const float*)d_in[1];   // [B, D]
    const float* U  = (const float*)d_in[2];   // [E, D, R]
    const float* V  = (const float*)d_in[3];   // [E, R, D]
    const float* C  = (const float*)d_in[4];   // [E, R, R]
    const float* b  = (const float*)d_in[5];   // [E, D]
    const float* Wg = (const float*)d_in[6];   // [E, D]
    const float* bg = (const float*)d_in[7];   // [E]
    float* out = (float*)d_out;

    cudaFuncSetAttribute(gemm_mma, cudaFuncAttributeMaxDynamicSharedMemorySize, SM_TOTAL);

    // bf16 conversions
    {
        uint2* xb;  cudaGetSymbolAddress((void**)&xb, g_Xb);
        uint2* vb;  cudaGetSymbolAddress((void**)&vb, g_Vb);
        cvt_kernel<<<(BB * 512 / 4 + 255) / 256, 256>>>((const float4*)x, xb, BB * 512 / 4);
        cvt_kernel<<<(512 * 512 / 4 + 255) / 256, 256>>>((const float4*)V, vb, 512 * 512 / 4);
    }
    uc_kernel<<<dim3(8, 8), 256>>>(U, C);
    gate_kernel<<<2048, 256>>>(x, Wg, bg);

    const __nv_bfloat16 *Xb, *Vb, *Hb, *Utb;
    cudaGetSymbolAddress((void**)&Xb, g_Xb);
    cudaGetSymbolAddress((void**)&Vb, g_Vb);
    cudaGetSymbolAddress((void**)&Hb, g_Hb);
    cudaGetSymbolAddress((void**)&Utb, g_Utb);

    // GEMM1: g_Hb = g * (x @ Vflat^T)
    gemm_mma<<<dim3(4, 128), 256, SM_TOTAL>>>(Xb, Vb, 1, nullptr, nullptr, nullptr, nullptr);
    // GEMM2: out = x0 * (g_Hb @ Ut^T) + g@b + x*sum(g)
    gemm_mma<<<dim3(4, 128), 256, SM_TOTAL>>>(Hb, Utb, 2, x0, x, b, out);
}

// round 10
// speedup vs baseline: 3.2034x; 1.2259x over previous
#include <cuda_runtime.h>
#include <cuda_bf16.h>
#include <cstdint>
#include <math.h>

// Problem sizes (fixed)
#define BB 16384
#define DD 512

// ---------------- scratch (device globals; no allocs allowed) ----------------
__device__ __nv_bfloat16 g_Vb[512 * 512];    // B1: V bf16, rows n=(e,r), k=d contiguous
__device__ __nv_bfloat16 g_Utb[512 * 512];   // B2: Ut[n=d][k=e*64+r] bf16 (C folded into U)
__device__ __nv_bfloat16 g_Xb[BB * 512];     // x bf16 (A operand GEMM1)
__device__ __nv_bfloat16 g_Hb[BB * 512];     // h = g*xv bf16 (A operand GEMM2)
__device__ float g_gate[BB * 8];             // softmax gates

// ---------------- helpers ----------------
__device__ __forceinline__ uint32_t smem_u32(const void* p) {
    uint32_t a;
    asm("{ .reg .u64 t; cvta.to.shared.u64 t, %1; cvt.u32.u64 %0, t; }" : "=r"(a) : "l"(p));
    return a;
}
__device__ __forceinline__ void cp16s(uint32_t s, const void* g) {
    asm volatile("cp.async.cg.shared.global [%0], [%1], 16;" :: "r"(s), "l"(g));
}
__device__ __forceinline__ void ldsm4(uint32_t* r, uint32_t addr) {
    asm volatile("ldmatrix.sync.aligned.m8n8.x4.shared.b16 {%0,%1,%2,%3}, [%4];"
        : "=r"(r[0]), "=r"(r[1]), "=r"(r[2]), "=r"(r[3]) : "r"(addr));
}
// m16n8k16 bf16 MMA, fp32 accum
__device__ __forceinline__ void mma_bf16(float* d, const uint32_t* a, uint32_t b0, uint32_t b1) {
    asm volatile(
        "mma.sync.aligned.m16n8k16.row.col.f32.bf16.bf16.f32 "
        "{%0,%1,%2,%3}, {%4,%5,%6,%7}, {%8,%9}, {%0,%1,%2,%3};"
        : "+f"(d[0]), "+f"(d[1]), "+f"(d[2]), "+f"(d[3])
        : "r"(a[0]), "r"(a[1]), "r"(a[2]), "r"(a[3]), "r"(b0), "r"(b1));
}

// smem geometry: chunk = 128 rows x 64 bf16 (128B) per operand, padded to 144B/row.
static constexpr int ROWB = 144;                 // bytes per smem row
static constexpr int STAGE_B = 128 * ROWB;       // 18432 B per operand per stage
static constexpr int OPS_B = 2 * STAGE_B;        // 36864 B per stage (A + B)
static constexpr int SM_TOTAL = 2 * OPS_B;       // 73728 B (2 stages)

// ---------------- convert fp32 -> bf16 (for V) ----------------
__global__ void cvt_kernel(const float4* __restrict__ in, uint2* __restrict__ out, int n4) {
    int i = blockIdx.x * blockDim.x + threadIdx.x;
    if (i >= n4) return;
    float4 v = in[i];
    __nv_bfloat162 lo = __floats2bfloat162_rn(v.x, v.y);
    __nv_bfloat162 hi = __floats2bfloat162_rn(v.z, v.w);
    uint2 o;
    o.x = *reinterpret_cast<uint32_t*>(&lo);
    o.y = *reinterpret_cast<uint32_t*>(&hi);
    out[i] = o;
}

// ---------------- prep: fold C into U -> Utb[n=d][k=e*64+r] (bf16) ----------------
__global__ void uc_kernel(const float* __restrict__ U, const float* __restrict__ C) {
    __shared__ float Cs[64][64];   // Cs[r][s]
    __shared__ float Us[64][65];   // Us[dl][s]
    int e = blockIdx.x;            // 0..7
    int d0 = blockIdx.y * 64;      // 0..511 step 64
    int t = threadIdx.x;           // 256 threads

    for (int i = t; i < 4096; i += 256) Cs[i >> 6][i & 63] = C[e * 4096 + i];
    for (int i = t; i < 4096; i += 256) Us[i >> 6][i & 63] = U[e * 32768 + d0 * 64 + i];
    __syncthreads();

    for (int o = t; o < 4096; o += 256) {
        int r = o >> 6, dl = o & 63;
        float s = 0.f;
#pragma unroll
        for (int ss = 0; ss < 64; ss++) s += Us[dl][ss] * Cs[r][ss];
        g_Utb[(size_t)(d0 + dl) * 512 + e * 64 + r] = __float2bfloat16(s);
    }
}

// ---------------- gate + x->bf16 fused: g = softmax(x@Wg^T + bg); g_Xb = bf16(x) ----------------
__global__ void gate_cvt_kernel(const float* __restrict__ x, const float* __restrict__ Wg,
                                const float* __restrict__ bg) {
    int warp = blockIdx.x * (blockDim.x >> 5) + (threadIdx.x >> 5);
    int lane = threadIdx.x & 31;
    if (warp >= BB) return;
    int m = warp;

    const float4* xr = reinterpret_cast<const float4*>(x + (size_t)m * 512);
    uint2* xb = reinterpret_cast<uint2*>(g_Xb + (size_t)m * 512);
    float acc[8] = {0.f, 0.f, 0.f, 0.f, 0.f, 0.f, 0.f, 0.f};
#pragma unroll
    for (int i = 0; i < 4; i++) {
        float4 xv = xr[lane + i * 32];
        // emit bf16 copy of x inline (single DRAM read of x serves both uses)
        __nv_bfloat162 lo = __floats2bfloat162_rn(xv.x, xv.y);
        __nv_bfloat162 hi = __floats2bfloat162_rn(xv.z, xv.w);
        uint2 o;
        o.x = *reinterpret_cast<uint32_t*>(&lo);
        o.y = *reinterpret_cast<uint32_t*>(&hi);
        xb[lane + i * 32] = o;
#pragma unroll
        for (int e = 0; e < 8; e++) {
            float4 wv = reinterpret_cast<const float4*>(Wg + e * 512)[lane + i * 32];
            acc[e] += xv.x * wv.x + xv.y * wv.y + xv.z * wv.z + xv.w * wv.w;
        }
    }
#pragma unroll
    for (int off = 16; off; off >>= 1)
#pragma unroll
        for (int e = 0; e < 8; e++) acc[e] += __shfl_xor_sync(0xFFFFFFFFu, acc[e], off);

    if (lane == 0) {
        float logit[8], mx = -1e30f;
#pragma unroll
        for (int e = 0; e < 8; e++) { logit[e] = acc[e] + bg[e]; mx = fmaxf(mx, logit[e]); }
        float ex[8], s = 0.f;
#pragma unroll
        for (int e = 0; e < 8; e++) { ex[e] = expf(logit[e] - mx); s += ex[e]; }
        float inv = 1.f / s;
#pragma unroll
        for (int e = 0; e < 8; e++) g_gate[m * 8 + e] = ex[e] * inv;
    }
}

// ---------------- bf16 mma.sync GEMM ----------------
// D[128,128] tile; 128 thr, 4 warps in 2(m) x 2(n), warp tile 64x64.
// K chunks of 64, 2-stage cp.async double buffer, 2 CTAs/SM.
// mode 1: A=g_Xb, B=g_Vb; epilogue h = g*xv -> g_Hb (bf16)
// mode 2: A=g_Hb, B=g_Utb; epilogue out = x0*gproj + g@b + x*sum(g)
__global__ __launch_bounds__(128, 2) void gemm_mma(const __nv_bfloat16* __restrict__ A,
                                                   const __nv_bfloat16* __restrict__ Bp,
                                                   int mode,
                                                   const float* __restrict__ x0,
                                                   const float* __restrict__ x,
                                                   const float* __restrict__ bbias,
                                                   float* __restrict__ out) {
    extern __shared__ __align__(16) float smemf[];
    const uint32_t sb = smem_u32(smemf);
    const int tid = threadIdx.x;
    const int wid = tid >> 5, lane = tid & 31;
    const int g = lane >> 2, tg = lane & 3;       // accum frag coords
    const int wm = wid & 1, wn = wid >> 1;        // warp m (0..1), n (0..1)
    const int n0 = blockIdx.x * 128, m0 = blockIdx.y * 128;

    float acc[4][8][4];
#pragma unroll
    for (int mi = 0; mi < 4; mi++)
#pragma unroll
        for (int ni = 0; ni < 8; ni++)
#pragma unroll
            for (int q = 0; q < 4; q++) acc[mi][ni][q] = 0.f;

    // ldmatrix lane->address maps (add stage*OPS_B + ks*32 at use)
    const int arow_l = (lane & 7) + ((lane >> 3) & 1) * 8;
    const int ahalf  = ((lane >> 4) & 1) * 16;
    uint32_t a_addr[4];
#pragma unroll
    for (int mi = 0; mi < 4; mi++)
        a_addr[mi] = sb + (uint32_t)(wm * 64 + mi * 16 + arow_l) * ROWB + ahalf;
    const int brow_l = (lane & 7) + ((lane >> 4) & 1) * 8;
    const int bhalf  = ((lane >> 3) & 1) * 16;
    uint32_t b_addr[4];
#pragma unroll
    for (int bj = 0; bj < 4; bj++)
        b_addr[bj] = sb + STAGE_B + (uint32_t)(wn * 64 + bj * 16 + brow_l) * ROWB + bhalf;

    // chunk load: 128 rows x 128B per operand; 16 cp16 per thread
#define LOADCHUNK(SLOT, KC) do {                                                         \
        const __nv_bfloat16* _ag = A  + (size_t)m0 * 512 + (KC) * 64;                    \
        const __nv_bfloat16* _bg = Bp + (size_t)n0 * 512 + (KC) * 64;                    \
        uint32_t _ab = sb + (SLOT) * OPS_B;                                              \
        uint32_t _bb = _ab + STAGE_B;                                                    \
        _Pragma("unroll")                                                                \
        for (int j = 0; j < 8; j++) {                                                    \
            int id = tid + j * 128;                                                      \
            int row = id >> 3, seg = id & 7;                                             \
            cp16s(_ab + row * ROWB + seg * 16, _ag + (size_t)row * 512 + seg * 8);       \
            cp16s(_bb + row * ROWB + seg * 16, _bg + (size_t)row * 512 + seg * 8);       \
        }                                                                                \
        asm volatile("cp.async.commit_group;");                                          \
    } while (0)

    LOADCHUNK(0, 0);

    for (int c = 0; c < 8; c++) {
        if (c < 7) LOADCHUNK((c + 1) & 1, c + 1);
        if (c < 7) asm volatile("cp.async.wait_group 1;");
        else       asm volatile("cp.async.wait_group 0;");
        __syncthreads();

        const uint32_t soff = (uint32_t)(c & 1) * OPS_B;
#pragma unroll
        for (int ks = 0; ks < 4; ks++) {
            const uint32_t ko = soff + ks * 32;
            uint32_t a[4][4];
#pragma unroll
            for (int mi = 0; mi < 4; mi++) ldsm4(a[mi], a_addr[mi] + ko);
            uint32_t b[4][4];
#pragma unroll
            for (int bj = 0; bj < 4; bj++) ldsm4(b[bj], b_addr[bj] + ko);
#pragma unroll
            for (int ni = 0; ni < 8; ni++) {
                uint32_t b0 = b[ni >> 1][(ni & 1) * 2];
                uint32_t b1 = b[ni >> 1][(ni & 1) * 2 + 1];
#pragma unroll
                for (int mi = 0; mi < 4; mi++) mma_bf16(acc[mi][ni], a[mi], b0, b1);
            }
        }
        if (c < 7) __syncthreads();   // protect buf (c+1)&1^1 = c&1 before next-iter overwrite
    }
#undef LOADCHUNK

    // ---------------- epilogue ----------------
    // acc[mi][ni]: rows r0 = m0+wm*64+mi*16+g (c0,c1), r1 = r0+8 (c2,c3);
    // cols = n0 + wn*64 + ni*8 + 2*tg (+1)
    if (mode == 1) {
        const int e_w = (n0 + wn * 64) >> 6;   // expert constant per warp column strip
#pragma unroll
        for (int mi = 0; mi < 4; mi++) {
            int r0 = m0 + wm * 64 + mi * 16 + g, r1 = r0 + 8;
            float g0 = g_gate[r0 * 8 + e_w];
            float g1 = g_gate[r1 * 8 + e_w];
#pragma unroll
            for (int ni = 0; ni < 8; ni++) {
                int cc = n0 + wn * 64 + ni * 8 + 2 * tg;
                __nv_bfloat162 h0 = __floats2bfloat162_rn(g0 * acc[mi][ni][0], g0 * acc[mi][ni][1]);
                __nv_bfloat162 h1 = __floats2bfloat162_rn(g1 * acc[mi][ni][2], g1 * acc[mi][ni][3]);
                *reinterpret_cast<__nv_bfloat162*>(&g_Hb[(size_t)r0 * 512 + cc]) = h0;
                *reinterpret_cast<__nv_bfloat162*>(&g_Hb[(size_t)r1 * 512 + cc]) = h1;
            }
        }
    } else {
        // stage b columns for this CTA: bs[e][0..127]
        __syncthreads();
        float* bs = smemf;
        for (int i = tid; i < 8 * 128; i += 128)
            bs[i] = bbias[(i >> 7) * 512 + n0 + (i & 127)];
        __syncthreads();

#pragma unroll
        for (int ni = 0; ni < 8; ni++) {
            int cl = wn * 64 + ni * 8 + 2 * tg;
            int cc = n0 + cl;
            float bc0[8], bc1[8];
#pragma unroll
            for (int e = 0; e < 8; e++) { bc0[e] = bs[e * 128 + cl]; bc1[e] = bs[e * 128 + cl + 1]; }
#pragma unroll
            for (int mi = 0; mi < 4; mi++) {
                int r0 = m0 + wm * 64 + mi * 16 + g;
#pragma unroll
                for (int rr = 0; rr < 2; rr++) {
                    int r = r0 + rr * 8;
                    float4 ga = *reinterpret_cast<const float4*>(g_gate + r * 8);
                    float4 gb = *reinterpret_cast<const float4*>(g_gate + r * 8 + 4);
                    float gs = ga.x + ga.y + ga.z + ga.w + gb.x + gb.y + gb.z + gb.w;
                    float q0 = ga.x * bc0[0] + ga.y * bc0[1] + ga.z * bc0[2] + ga.w * bc0[3]
                             + gb.x * bc0[4] + gb.y * bc0[5] + gb.z * bc0[6] + gb.w * bc0[7];
                    float q1 = ga.x * bc1[0] + ga.y * bc1[1] + ga.z * bc1[2] + ga.w * bc1[3]
                             + gb.x * bc1[4] + gb.y * bc1[5] + gb.z * bc1[6] + gb.w * bc1[7];
                    size_t off = (size_t)r * 512 + cc;
                    float2 xv0 = *reinterpret_cast<const float2*>(x0 + off);
                    float2 xv  = *reinterpret_cast<const float2*>(x + off);
                    float a0 = acc[mi][ni][rr ? 2 : 0];
                    float a1 = acc[mi][ni][rr ? 3 : 1];
                    float2 o;
                    o.x = fmaf(xv0.x, a0, fmaf(xv.x, gs, q0));
                    o.y = fmaf(xv0.y, a1, fmaf(xv.y, gs, q1));
                    *reinterpret_cast<float2*>(out + off) = o;
                }
            }
        }
    }
}

// ---------------- launch ----------------
extern "C" void kernel_launch(void* const* d_in, const int* in_sizes, int n_in,
                              void* d_out, int out_size) {
    const float* x0 = (const float*)d_in[0];   // [B, D]
    const float* x  = (const float*)d_in[1];   // [B, D]
    const float* U  = (const float*)d_in[2];   // [E, D, R]
    const float* V  = (const float*)d_in[3];   // [E, R, D]
    const float* C  = (const float*)d_in[4];   // [E, R, R]
    const float* b  = (const float*)d_in[5];   // [E, D]
    const float* Wg = (const float*)d_in[6];   // [E, D]
    const float* bg = (const float*)d_in[7];   // [E]
    float* out = (float*)d_out;

    cudaFuncSetAttribute(gemm_mma, cudaFuncAttributeMaxDynamicSharedMemorySize, SM_TOTAL);

    // V -> bf16
    {
        uint2* vb;  cudaGetSymbolAddress((void**)&vb, g_Vb);
        cvt_kernel<<<(512 * 512 / 4 + 255) / 256, 256>>>((const float4*)V, vb, 512 * 512 / 4);
    }
    uc_kernel<<<dim3(8, 8), 256>>>(U, C);
    gate_cvt_kernel<<<2048, 256>>>(x, Wg, bg);   // gates + x->bf16 in one pass

    const __nv_bfloat16 *Xb, *Vb, *Hb, *Utb;
    cudaGetSymbolAddress((void**)&Xb, g_Xb);
    cudaGetSymbolAddress((void**)&Vb, g_Vb);
    cudaGetSymbolAddress((void**)&Hb, g_Hb);
    cudaGetSymbolAddress((void**)&Utb, g_Utb);

    // GEMM1: g_Hb = g * (x @ Vflat^T)
    gemm_mma<<<dim3(4, 128), 128, SM_TOTAL>>>(Xb, Vb, 1, nullptr, nullptr, nullptr, nullptr);
    // GEMM2: out = x0 * (g_Hb @ Ut^T) + g@b + x*sum(g)
    gemm_mma<<<dim3(4, 128), 128, SM_TOTAL>>>(Hb, Utb, 2, x0, x, b, out);
}